// round 15
// baseline (speedup 1.0000x reference)
#include <cuda_runtime.h>
#include <cuda_fp16.h>
#include <math.h>
#include <stdint.h>

// Problem dims
#define TT   512
#define BB   128
#define II   512
#define HH   512
#define G4   2048
#define NBLK 128         // persistent blocks for recurrence
#define TBH  ((size_t)TT * BB * HH)

// ---------------------------------------------------------------------------
// Device scratch (allocation-free rule)
// ---------------------------------------------------------------------------
__device__ __half    g_Xf[(size_t)TT * BB * II];    // 64MB (f16 x)
__device__ __half    g_Hf[2][BB * HH];              // h (f16), double-buffered
__device__ unsigned  g_syncg[128];                  // per-group barrier ctrs (use [gb*32])

// ---------------------------------------------------------------------------
// Helpers
// ---------------------------------------------------------------------------
__device__ __forceinline__ uint32_t smem_u32(const void* p) {
    return (uint32_t)__cvta_generic_to_shared(p);
}
__device__ __forceinline__ void ldmx4(uint32_t& r0, uint32_t& r1, uint32_t& r2, uint32_t& r3,
                                      uint32_t addr) {
    asm volatile("ldmatrix.sync.aligned.m8n8.x4.shared.b16 {%0,%1,%2,%3}, [%4];"
                 : "=r"(r0), "=r"(r1), "=r"(r2), "=r"(r3) : "r"(addr));
}
__device__ __forceinline__ void mma_f16(float* d, const uint32_t* a, const uint32_t* b) {
    asm volatile(
        "mma.sync.aligned.m16n8k16.row.col.f32.f16.f16.f32 "
        "{%0,%1,%2,%3}, {%4,%5,%6,%7}, {%8,%9}, {%0,%1,%2,%3};"
        : "+f"(d[0]), "+f"(d[1]), "+f"(d[2]), "+f"(d[3])
        : "r"(a[0]), "r"(a[1]), "r"(a[2]), "r"(a[3]), "r"(b[0]), "r"(b[1]));
}

// ---------------------------------------------------------------------------
// convert_init: x -> f16, zero barriers.
// ---------------------------------------------------------------------------
__global__ void convert_init(const float* __restrict__ X)
{
    size_t i0 = (size_t)blockIdx.x * blockDim.x + threadIdx.x;
    size_t stride = (size_t)gridDim.x * blockDim.x;
    const size_t NX4 = (size_t)TT * BB * II / 4;

    for (size_t i = i0; i < NX4; i += stride) {
        float4 v = ((const float4*)X)[i];
        uint32_t a = (uint32_t)__half_as_ushort(__float2half_rn(v.x)) |
                     ((uint32_t)__half_as_ushort(__float2half_rn(v.y)) << 16);
        uint32_t b = (uint32_t)__half_as_ushort(__float2half_rn(v.z)) |
                     ((uint32_t)__half_as_ushort(__float2half_rn(v.w)) << 16);
        ((uint2*)g_Xf)[i] = make_uint2(a, b);
    }
    for (size_t i = i0; i < 128; i += stride) g_syncg[i] = 0u;
}

// ---------------------------------------------------------------------------
// Fully-fused persistent LSTM. 128 blocks = 32 h-col groups x 4 batch groups.
// Block (gh, gb): gate cols {q*512 + hc0..hc0+15}, batches [b0, b0+32).
// Per step t:
//   d = dxc (x@W_ih from previous iteration's overlap slot)
//   d += h(t-1) @ W_hh  (64 mma, fragment-identical layout)
//   elementwise (+bias) -> h(t) -> out + g_Hf
//   [overlap slot, before barrier] load x[t+1], dxc = x@W_ih (64 mma)
//   per-group barrier
// No g_xg intermediate; input-projection GEMM hidden in barrier slack.
// ---------------------------------------------------------------------------
#define RW_PITCH 520
#define RS_WIH  0
#define RS_WHH  66560
#define RS_XS   133120
#define RS_HS   166400
#define RS_CS   199680
#define RS_HST  208128
#define RS_BIAS 210304
#define RS_TOT  210560

__global__ void __launch_bounds__(256, 1) lstm_rec(const float* __restrict__ Whh,
                                                   const float* __restrict__ Wih,
                                                   const float* __restrict__ b_ih,
                                                   const float* __restrict__ b_hh,
                                                   float* __restrict__ out,
                                                   int tail)
{
    extern __shared__ __align__(16) char rsm[];
    __half* Wsi = (__half*)(rsm + RS_WIH);
    __half* Wsh = (__half*)(rsm + RS_WHH);
    float*  Cs  = (float*)(rsm + RS_CS);      // [64 col][33] transposed
    float* hstage = (float*)(rsm + RS_HST);   // [32 b][17]
    float* biasS  = (float*)(rsm + RS_BIAS);  // [64]
    const uint32_t uSM = smem_u32(rsm);

    const int tid  = threadIdx.x;
    const int lane = tid & 31;
    const int w    = tid >> 5;
    const int gid  = lane >> 2;
    const int tig  = lane & 3;
    const int gh   = blockIdx.x & 31;   // h-col group
    const int gb   = blockIdx.x >> 5;   // batch group (independent recurrence)
    const int hc0  = gh * 16;
    const int b0   = gb * 32;
    volatile unsigned* mybar = &g_syncg[gb * 32];

    // Load W_ih and W_hh slices (f16): W*[j][k], n = (j>>4)*512 + hc0 + (j&15)
    for (int idx = tid; idx < 64 * 512; idx += 256) {
        int j = idx >> 9, k = idx & 511;
        int n = (j >> 4) * 512 + hc0 + (j & 15);
        Wsi[j * RW_PITCH + k] = __float2half_rn(Wih[(size_t)n * II + k]);
        Wsh[j * RW_PITCH + k] = __float2half_rn(Whh[(size_t)n * HH + k]);
    }
    if (tid < 64) {
        int n = (tid >> 4) * 512 + hc0 + (tid & 15);
        biasS[tid] = b_ih[n] + b_hh[n];
    }
    __syncthreads();

    const int wm  = w & 1;              // m-tile (16 batches)
    const int wn  = w >> 1;             // n-group (16 gate cols)
    const int a_r = lane & 15, a_c = (lane >> 4) << 3;
    // B ldmatrix.x4 lane mapping: m0=nt0/k0-7, m1=nt0/k8-15, m2=nt1/k0-7, m3=nt1/k8-15
    const int b_nrow = wn * 16 + ((lane >> 4) << 3) + (lane & 7);
    const int b_koff = ((lane >> 3) & 1) << 3;
    const int e_b = tid & 31;           // local batch
    const int e_r = tid >> 5;           // ci base (handles ci = e_r, e_r+8)
    float creg[2] = {0.f, 0.f};
    float dxc[2][4];                    // carried x-projection fragments

    // prologue: load x[0] slice, compute dxc = x0 @ W_ih^T
    {
#pragma unroll
        for (int j = 0; j < 8; ++j) {
            int idx = tid + 256 * j;
            int row = idx >> 6, seg = idx & 63;
            *(uint4*)(rsm + RS_XS + (row * RW_PITCH + seg * 8) * 2) =
                *(const uint4*)(g_Xf + (size_t)(b0 + row) * II + seg * 8);
        }
        __syncthreads();
        float dx[2][4] = {{0.f, 0.f, 0.f, 0.f}};
#pragma unroll 4
        for (int kk = 0; kk < 32; ++kk) {
            const int kb = kk * 16;
            uint32_t ah[4];
            uint32_t aoff = (uint32_t)(((wm * 16 + a_r) * RW_PITCH + kb + a_c) * 2);
            ldmx4(ah[0], ah[1], ah[2], ah[3], uSM + RS_XS + aoff);
            uint32_t boff = (uint32_t)((b_nrow * RW_PITCH + kb + b_koff) * 2);
            uint32_t bh4[4];
            ldmx4(bh4[0], bh4[1], bh4[2], bh4[3], uSM + RS_WIH + boff);
            mma_f16(dx[0], ah, bh4 + 0);
            mma_f16(dx[1], ah, bh4 + 2);
        }
#pragma unroll
        for (int nt = 0; nt < 2; ++nt)
#pragma unroll
            for (int i = 0; i < 4; ++i) dxc[nt][i] = dx[nt][i];
    }

    for (int t = 0; t < TT; ++t) {
        float d[2][4];
#pragma unroll
        for (int nt = 0; nt < 2; ++nt)
#pragma unroll
            for (int i = 0; i < 4; ++i) d[nt][i] = dxc[nt][i];

        if (t > 0) {
            // load h slice: 32 rows x 512 f16 = 2048 uint4, one shot
            const __half* srcH = g_Hf[(t - 1) & 1];
#pragma unroll
            for (int j = 0; j < 8; ++j) {
                int idx = tid + 256 * j;
                int row = idx >> 6, seg = idx & 63;
                *(uint4*)(rsm + RS_HS + (row * RW_PITCH + seg * 8) * 2) =
                    *(const uint4*)(srcH + (size_t)(b0 + row) * HH + seg * 8);
            }
            __syncthreads();

#pragma unroll 4
            for (int kk = 0; kk < 32; ++kk) {
                const int kb = kk * 16;
                uint32_t ah[4];
                uint32_t aoff = (uint32_t)(((wm * 16 + a_r) * RW_PITCH + kb + a_c) * 2);
                ldmx4(ah[0], ah[1], ah[2], ah[3], uSM + RS_HS + aoff);
                uint32_t boff = (uint32_t)((b_nrow * RW_PITCH + kb + b_koff) * 2);
                uint32_t bh4[4];
                ldmx4(bh4[0], bh4[1], bh4[2], bh4[3], uSM + RS_WHH + boff);
                mma_f16(d[0], ah, bh4 + 0);
                mma_f16(d[1], ah, bh4 + 2);
            }
        }

        // dump gate fragments transposed: Cs[col][b]
        {
            const int arow = wm * 16 + gid;
#pragma unroll
            for (int nt = 0; nt < 2; ++nt) {
                int c0 = wn * 16 + nt * 8 + 2 * tig;
                Cs[c0 * 33 + arow]           = d[nt][0];
                Cs[(c0 + 1) * 33 + arow]     = d[nt][1];
                Cs[c0 * 33 + arow + 8]       = d[nt][2];
                Cs[(c0 + 1) * 33 + arow + 8] = d[nt][3];
            }
        }
        __syncthreads();

        // Fused fp32 LSTM elementwise (+bias) -> h to smem stage
#pragma unroll
        for (int pi = 0; pi < 2; ++pi) {
            int ci = e_r + pi * 8;
            float gate[4];
#pragma unroll
            for (int q = 0; q < 4; ++q)
                gate[q] = Cs[(q * 16 + ci) * 33 + e_b] + biasS[q * 16 + ci];
            float ig = 1.0f / (1.0f + __expf(-gate[0]));
            float fg = 1.0f / (1.0f + __expf(-gate[1]));
            float gg = tanhf(gate[2]);
            float og = 1.0f / (1.0f + __expf(-gate[3]));
            float cn = fg * creg[pi] + ig * gg;
            creg[pi] = cn;
            hstage[e_b * 17 + ci] = og * tanhf(cn);
        }
        __syncthreads();

        // coalesced h writes: float4 out + uint2 f16 h (4 cols per thread)
        if (tid < 128) {
            int bl_ = tid >> 2, qd = tid & 3;
            const float* hp = &hstage[bl_ * 17 + qd * 4];
            float h0 = hp[0], h1 = hp[1], h2 = hp[2], h3 = hp[3];
            *(float4*)(out + (size_t)t * BB * HH + (size_t)(b0 + bl_) * HH + hc0 + qd * 4) =
                make_float4(h0, h1, h2, h3);
            uint32_t p0 = (uint32_t)__half_as_ushort(__float2half_rn(h0)) |
                          ((uint32_t)__half_as_ushort(__float2half_rn(h1)) << 16);
            uint32_t p1 = (uint32_t)__half_as_ushort(__float2half_rn(h2)) |
                          ((uint32_t)__half_as_ushort(__float2half_rn(h3)) << 16);
            *(uint2*)(g_Hf[t & 1] + (size_t)(b0 + bl_) * HH + hc0 + qd * 4) =
                make_uint2(p0, p1);
        }

        // overlap slot (h-independent): load x[t+1], dxc = x@W_ih.
        // This fills the barrier-wait bubble with the input-projection GEMM.
        if (t + 1 < TT) {
            const __half* srcX = g_Xf + (size_t)(t + 1) * BB * II;
#pragma unroll
            for (int j = 0; j < 8; ++j) {
                int idx = tid + 256 * j;
                int row = idx >> 6, seg = idx & 63;
                *(uint4*)(rsm + RS_XS + (row * RW_PITCH + seg * 8) * 2) =
                    *(const uint4*)(srcX + (size_t)(b0 + row) * II + seg * 8);
            }
            __syncthreads();
            float dx[2][4] = {{0.f, 0.f, 0.f, 0.f}};
#pragma unroll 4
            for (int kk = 0; kk < 32; ++kk) {
                const int kb = kk * 16;
                uint32_t ah[4];
                uint32_t aoff = (uint32_t)(((wm * 16 + a_r) * RW_PITCH + kb + a_c) * 2);
                ldmx4(ah[0], ah[1], ah[2], ah[3], uSM + RS_XS + aoff);
                uint32_t boff = (uint32_t)((b_nrow * RW_PITCH + kb + b_koff) * 2);
                uint32_t bh4[4];
                ldmx4(bh4[0], bh4[1], bh4[2], bh4[3], uSM + RS_WIH + boff);
                mma_f16(dx[0], ah, bh4 + 0);
                mma_f16(dx[1], ah, bh4 + 2);
            }
#pragma unroll
            for (int nt = 0; nt < 2; ++nt)
#pragma unroll
                for (int i = 0; i < 4; ++i) dxc[nt][i] = dx[nt][i];
        }

        // per-group barrier (only the 32 same-gb blocks interact)
        __syncthreads();
        if (tid == 0) {
            __threadfence();
            atomicAdd((unsigned*)mybar, 1u);
            unsigned target = (unsigned)(t + 1) * 32u;
            while (*mybar < target) { }
            __threadfence();
        }
        __syncthreads();
    }

    // tail: hT copy + cT from registers
    if (tail) {
#pragma unroll
        for (int pi = 0; pi < 2; ++pi) {
            int ci = e_r + pi * 8;
            size_t idx = (size_t)(b0 + e_b) * HH + hc0 + ci;
            out[TBH + idx]           = out[(size_t)(TT - 1) * BB * HH + idx];
            out[TBH + BB * HH + idx] = creg[pi];
        }
    }
}

// ---------------------------------------------------------------------------
extern "C" void kernel_launch(void* const* d_in, const int* in_sizes, int n_in,
                              void* d_out, int out_size)
{
    const float* input = (const float*)d_in[0];
    /* d_in[1] = time, unused by the base cell */
    const float* W_ih  = (const float*)d_in[2];
    const float* W_hh  = (const float*)d_in[3];
    const float* b_ih  = (const float*)d_in[4];
    const float* b_hh  = (const float*)d_in[5];
    float* out = (float*)d_out;

    int tail = ((size_t)out_size >= TBH + 2ull * BB * HH) ? 1 : 0;

    convert_init<<<2048, 256>>>(input);

    cudaFuncSetAttribute(lstm_rec, cudaFuncAttributeMaxDynamicSharedMemorySize, RS_TOT);
    lstm_rec<<<NBLK, 256, RS_TOT>>>(W_hh, W_ih, b_ih, b_hh, out, tail);
}